// round 4
// baseline (speedup 1.0000x reference)
#include <cuda_runtime.h>
#include <math.h>

#define NN   100000
#define EE   640000
#define HH   128
#define EMBD 96
#define SELD 32
#define PDIM 64
#define NT   3
#define GITERS 6
#define WTS  388   // padded row pitch for transposed GRU weights in smem (16B aligned, 4-way-max conflicts on transpose writes)

// ---------------- device scratch (no allocations allowed) ----------------
__device__ float d_h0 [NN * HH];
__device__ float d_hA [NN * HH];
__device__ float d_hB [NN * HH];
__device__ float d_agg[NN * HH];
__device__ float d_gi [NN * 3 * HH];
__device__ float d_gate[EE * HH];          // 327 MB
__device__ float d_cnt[NN];
__device__ float d_inv[NN];

__device__ __forceinline__ float sigf(float x) { return 1.0f / (1.0f + __expf(-x)); }

// ---------------- setup kernels ----------------
__global__ void k_zero_cnt() {
    int i = blockIdx.x * blockDim.x + threadIdx.x;
    if (i < NN) d_cnt[i] = 0.0f;
}

__global__ void k_h0(const int* __restrict__ xidx, const float* __restrict__ sel,
                     const float* __restrict__ emb) {
    int t = blockIdx.x * blockDim.x + threadIdx.x;      // NN*32 threads, float4 each
    if (t >= NN * 32) return;
    int n = t >> 5;
    int q = (t & 31) * 4;
    float4 v;
    if (q < EMBD) v = *(const float4*)&emb[(long long)xidx[n] * EMBD + q];
    else          v = *(const float4*)&sel[n * SELD + (q - EMBD)];
    *(float4*)&d_h0[n * HH + q] = v;
    *(float4*)&d_hA[n * HH + q] = v;
}

__global__ void k_deg(const int* __restrict__ dst) {
    int e = blockIdx.x * blockDim.x + threadIdx.x;
    if (e < EE) atomicAdd(&d_cnt[dst[e]], 1.0f);
}

__global__ void k_inv() {
    int i = blockIdx.x * blockDim.x + threadIdx.x;
    if (i < NN) d_inv[i] = 1.0f / fmaxf(d_cnt[i], 1.0f);
}

__global__ void k_zero_agg() {
    int i = blockIdx.x * blockDim.x + threadIdx.x;      // NN*HH/4 float4 stores
    if (i < NN * HH / 4) ((float4*)d_agg)[i] = make_float4(0.f, 0.f, 0.f, 0.f);
}

// gate[e, :] = 2*sigmoid(pos_enc[pos[e]] @ Wg + bg)      warp-per-edge, Wg in smem
__global__ __launch_bounds__(256) void k_gate(const int* __restrict__ pos,
                                              const float* __restrict__ pe,
                                              const float* __restrict__ Wg,
                                              const float* __restrict__ bg) {
    extern __shared__ float sm[];
    float* wg  = sm;                 // 64*128
    float* bgs = wg + PDIM * HH;     // 128
    float* st  = bgs + HH;           // 8*64 per-warp staging
    for (int i = threadIdx.x; i < PDIM * HH; i += blockDim.x) wg[i] = Wg[i];
    for (int i = threadIdx.x; i < HH;        i += blockDim.x) bgs[i] = bg[i];
    __syncthreads();
    int lane = threadIdx.x & 31, warp = threadIdx.x >> 5;
    float* ps = st + warp * PDIM;
    int gw = blockIdx.x * (blockDim.x >> 5) + warp;
    int nw = gridDim.x * (blockDim.x >> 5);
    for (int e = gw; e < EE; e += nw) {
        int p = pos[e];
        if (lane < 16) *(float4*)&ps[4 * lane] = *(const float4*)&pe[p * PDIM + 4 * lane];
        __syncwarp();
        float4 a = make_float4(0.f, 0.f, 0.f, 0.f);
        #pragma unroll 8
        for (int k = 0; k < PDIM; k++) {
            float pv = ps[k];
            float4 w = *(const float4*)&wg[k * HH + 4 * lane];
            a.x += pv * w.x; a.y += pv * w.y; a.z += pv * w.z; a.w += pv * w.w;
        }
        float4 b = *(const float4*)&bgs[4 * lane];
        float4 g;
        g.x = 2.0f * sigf(a.x + b.x);
        g.y = 2.0f * sigf(a.y + b.y);
        g.z = 2.0f * sigf(a.z + b.z);
        g.w = 2.0f * sigf(a.w + b.w);
        *(float4*)&d_gate[e * HH + 4 * lane] = g;
        __syncwarp();
    }
}

// per-edge: msg = (h[src]*gate[e]) @ Wt[t] + bt[t]; atomicAdd(msg*inv[dst]) into agg
__global__ __launch_bounds__(256) void k_edge(const int* __restrict__ src,
                                              const int* __restrict__ dst,
                                              const int* __restrict__ et,
                                              const float* __restrict__ Wt,
                                              const float* __restrict__ bt,
                                              int flip) {
    extern __shared__ float sm[];
    float* wts = sm;                       // 3*128*128
    float* bts = wts + NT * HH * HH;       // 3*128
    float* vst = bts + NT * HH;            // 8*128 per-warp staging
    for (int i = threadIdx.x; i < NT * HH * HH; i += blockDim.x) wts[i] = Wt[i];
    for (int i = threadIdx.x; i < NT * HH;      i += blockDim.x) bts[i] = bt[i];
    __syncthreads();
    const float* __restrict__ h = flip ? d_hB : d_hA;
    int lane = threadIdx.x & 31, warp = threadIdx.x >> 5;
    float* v = vst + warp * HH;
    int gw = blockIdx.x * (blockDim.x >> 5) + warp;
    int nw = gridDim.x * (blockDim.x >> 5);
    for (int e = gw; e < EE; e += nw) {
        int s = src[e], d = dst[e], t = et[e];
        float4 hv = *(const float4*)&h[s * HH + 4 * lane];
        float4 gv = *(const float4*)&d_gate[e * HH + 4 * lane];
        *(float4*)&v[4 * lane] = make_float4(hv.x * gv.x, hv.y * gv.y, hv.z * gv.z, hv.w * gv.w);
        __syncwarp();
        const float* W = wts + t * HH * HH;
        float4 a0 = make_float4(0.f,0.f,0.f,0.f), a1 = a0, a2 = a0, a3 = a0;
        #pragma unroll 8
        for (int k = 0; k < HH; k += 4) {
            float4 x  = *(const float4*)&v[k];
            float4 w0 = *(const float4*)&W[(k + 0) * HH + 4 * lane];
            float4 w1 = *(const float4*)&W[(k + 1) * HH + 4 * lane];
            float4 w2 = *(const float4*)&W[(k + 2) * HH + 4 * lane];
            float4 w3 = *(const float4*)&W[(k + 3) * HH + 4 * lane];
            a0.x += x.x * w0.x; a0.y += x.x * w0.y; a0.z += x.x * w0.z; a0.w += x.x * w0.w;
            a1.x += x.y * w1.x; a1.y += x.y * w1.y; a1.z += x.y * w1.z; a1.w += x.y * w1.w;
            a2.x += x.z * w2.x; a2.y += x.z * w2.y; a2.z += x.z * w2.z; a2.w += x.z * w2.w;
            a3.x += x.w * w3.x; a3.y += x.w * w3.y; a3.z += x.w * w3.z; a3.w += x.w * w3.w;
        }
        float invd = d_inv[d];
        float4 b = *(const float4*)&bts[t * HH + 4 * lane];
        float ox = (a0.x + a1.x + a2.x + a3.x + b.x) * invd;
        float oy = (a0.y + a1.y + a2.y + a3.y + b.y) * invd;
        float oz = (a0.z + a1.z + a2.z + a3.z + b.z) * invd;
        float ow = (a0.w + a1.w + a2.w + a3.w + b.w) * invd;
        float* ap = &d_agg[d * HH + 4 * lane];
        atomicAdd(ap + 0, ox);
        atomicAdd(ap + 1, oy);
        atomicAdd(ap + 2, oz);
        atomicAdd(ap + 3, ow);
        __syncwarp();
    }
}

// gi = agg @ W_ih^T + b_ih   (W_ih transposed into smem, warp-per-node)
__global__ __launch_bounds__(256) void k_gi(const float* __restrict__ Wih,
                                            const float* __restrict__ bih) {
    extern __shared__ float sm[];
    float* wt  = sm;                    // [128][WTS]
    float* bs  = wt + HH * WTS;         // 384
    float* xst = bs + 3 * HH;           // 8*128
    for (int i = threadIdx.x; i < 3 * HH * HH; i += blockDim.x) {
        int j = i >> 7, k = i & 127;
        wt[k * WTS + j] = Wih[i];
    }
    for (int i = threadIdx.x; i < 3 * HH; i += blockDim.x) bs[i] = bih[i];
    __syncthreads();
    int lane = threadIdx.x & 31, warp = threadIdx.x >> 5;
    float* xs = xst + warp * HH;
    int gw = blockIdx.x * (blockDim.x >> 5) + warp;
    int nw = gridDim.x * (blockDim.x >> 5);
    for (int n = gw; n < NN; n += nw) {
        *(float4*)&xs[4 * lane] = *(const float4*)&d_agg[n * HH + 4 * lane];
        __syncwarp();
        float4 m0 = make_float4(0.f,0.f,0.f,0.f), m1 = m0, m2 = m0;
        #pragma unroll 4
        for (int k = 0; k < HH; k++) {
            float xv = xs[k];
            const float* row = &wt[k * WTS];
            float4 w0 = *(const float4*)&row[      4 * lane];
            float4 w1 = *(const float4*)&row[128 + 4 * lane];
            float4 w2 = *(const float4*)&row[256 + 4 * lane];
            m0.x += xv * w0.x; m0.y += xv * w0.y; m0.z += xv * w0.z; m0.w += xv * w0.w;
            m1.x += xv * w1.x; m1.y += xv * w1.y; m1.z += xv * w1.z; m1.w += xv * w1.w;
            m2.x += xv * w2.x; m2.y += xv * w2.y; m2.z += xv * w2.z; m2.w += xv * w2.w;
        }
        float4 b0 = *(const float4*)&bs[      4 * lane];
        float4 b1 = *(const float4*)&bs[128 + 4 * lane];
        float4 b2 = *(const float4*)&bs[256 + 4 * lane];
        float* gp = &d_gi[n * 3 * HH];
        *(float4*)&gp[      4 * lane] = make_float4(m0.x+b0.x, m0.y+b0.y, m0.z+b0.z, m0.w+b0.w);
        *(float4*)&gp[128 + 4 * lane] = make_float4(m1.x+b1.x, m1.y+b1.y, m1.z+b1.z, m1.w+b1.w);
        *(float4*)&gp[256 + 4 * lane] = make_float4(m2.x+b2.x, m2.y+b2.y, m2.z+b2.z, m2.w+b2.w);
        __syncwarp();
    }
}

// gh = h @ W_hh^T + b_hh, then fused GRU combine -> h_next
__global__ __launch_bounds__(256) void k_gh(const float* __restrict__ Whh,
                                            const float* __restrict__ bhh,
                                            int flip) {
    extern __shared__ float sm[];
    float* wt  = sm;
    float* bs  = wt + HH * WTS;
    float* xst = bs + 3 * HH;
    for (int i = threadIdx.x; i < 3 * HH * HH; i += blockDim.x) {
        int j = i >> 7, k = i & 127;
        wt[k * WTS + j] = Whh[i];
    }
    for (int i = threadIdx.x; i < 3 * HH; i += blockDim.x) bs[i] = bhh[i];
    __syncthreads();
    const float* __restrict__ h = flip ? d_hB : d_hA;
    float* __restrict__ hn      = flip ? d_hA : d_hB;
    int lane = threadIdx.x & 31, warp = threadIdx.x >> 5;
    float* xs = xst + warp * HH;
    int gw = blockIdx.x * (blockDim.x >> 5) + warp;
    int nw = gridDim.x * (blockDim.x >> 5);
    for (int n = gw; n < NN; n += nw) {
        float4 hh = *(const float4*)&h[n * HH + 4 * lane];
        *(float4*)&xs[4 * lane] = hh;
        __syncwarp();
        float4 m0 = make_float4(0.f,0.f,0.f,0.f), m1 = m0, m2 = m0;
        #pragma unroll 4
        for (int k = 0; k < HH; k++) {
            float xv = xs[k];
            const float* row = &wt[k * WTS];
            float4 w0 = *(const float4*)&row[      4 * lane];
            float4 w1 = *(const float4*)&row[128 + 4 * lane];
            float4 w2 = *(const float4*)&row[256 + 4 * lane];
            m0.x += xv * w0.x; m0.y += xv * w0.y; m0.z += xv * w0.z; m0.w += xv * w0.w;
            m1.x += xv * w1.x; m1.y += xv * w1.y; m1.z += xv * w1.z; m1.w += xv * w1.w;
            m2.x += xv * w2.x; m2.y += xv * w2.y; m2.z += xv * w2.z; m2.w += xv * w2.w;
        }
        float4 b0 = *(const float4*)&bs[      4 * lane];
        float4 b1 = *(const float4*)&bs[128 + 4 * lane];
        float4 b2 = *(const float4*)&bs[256 + 4 * lane];
        const float* gp = &d_gi[n * 3 * HH];
        float4 g0 = *(const float4*)&gp[      4 * lane];
        float4 g1 = *(const float4*)&gp[128 + 4 * lane];
        float4 g2 = *(const float4*)&gp[256 + 4 * lane];
        float4 o;
        {
            float r = sigf(g0.x + m0.x + b0.x);
            float z = sigf(g1.x + m1.x + b1.x);
            float t = tanhf(g2.x + r * (m2.x + b2.x));
            o.x = (1.0f - z) * t + z * hh.x;
        }
        {
            float r = sigf(g0.y + m0.y + b0.y);
            float z = sigf(g1.y + m1.y + b1.y);
            float t = tanhf(g2.y + r * (m2.y + b2.y));
            o.y = (1.0f - z) * t + z * hh.y;
        }
        {
            float r = sigf(g0.z + m0.z + b0.z);
            float z = sigf(g1.z + m1.z + b1.z);
            float t = tanhf(g2.z + r * (m2.z + b2.z));
            o.z = (1.0f - z) * t + z * hh.z;
        }
        {
            float r = sigf(g0.w + m0.w + b0.w);
            float z = sigf(g1.w + m1.w + b1.w);
            float t = tanhf(g2.w + r * (m2.w + b2.w));
            o.w = (1.0f - z) * t + z * hh.w;
        }
        *(float4*)&hn[n * HH + 4 * lane] = o;
        __syncwarp();
    }
}

// logits = relu([h, h0] @ W1 + b1) @ W2 + b2
__global__ __launch_bounds__(256) void k_out(const float* __restrict__ W1,
                                             const float* __restrict__ b1,
                                             const float* __restrict__ W2,
                                             const float* __restrict__ b2,
                                             float* __restrict__ out) {
    extern __shared__ float sm[];
    float* w1  = sm;                 // 256*128
    float* b1s = w1 + 2 * HH * HH;   // 128
    float* fst = b1s + HH;           // 8*256
    for (int i = threadIdx.x; i < 2 * HH * HH; i += blockDim.x) w1[i] = W1[i];
    for (int i = threadIdx.x; i < HH;          i += blockDim.x) b1s[i] = b1[i];
    __syncthreads();
    int lane = threadIdx.x & 31, warp = threadIdx.x >> 5;
    float* fs = fst + warp * 2 * HH;
    int gw = blockIdx.x * (blockDim.x >> 5) + warp;
    int nw = gridDim.x * (blockDim.x >> 5);
    for (int n = gw; n < NN; n += nw) {
        *(float4*)&fs[      4 * lane] = *(const float4*)&d_hA[n * HH + 4 * lane];
        *(float4*)&fs[128 + 4 * lane] = *(const float4*)&d_h0[n * HH + 4 * lane];
        __syncwarp();
        float4 a = make_float4(0.f,0.f,0.f,0.f);
        #pragma unroll 8
        for (int k = 0; k < 2 * HH; k++) {
            float fv = fs[k];
            float4 w = *(const float4*)&w1[k * HH + 4 * lane];
            a.x += fv * w.x; a.y += fv * w.y; a.z += fv * w.z; a.w += fv * w.w;
        }
        float4 bb = *(const float4*)&b1s[4 * lane];
        float4 r;
        r.x = fmaxf(a.x + bb.x, 0.f);
        r.y = fmaxf(a.y + bb.y, 0.f);
        r.z = fmaxf(a.z + bb.z, 0.f);
        r.w = fmaxf(a.w + bb.w, 0.f);
        float4 w2 = *(const float4*)&W2[4 * lane];
        float p = r.x * w2.x + r.y * w2.y + r.z * w2.z + r.w * w2.w;
        #pragma unroll
        for (int o = 16; o > 0; o >>= 1) p += __shfl_xor_sync(0xFFFFFFFFu, p, o);
        if (lane == 0) out[n] = p + b2[0];
        __syncwarp();
    }
}

// ---------------- launch ----------------
extern "C" void kernel_launch(void* const* d_in, const int* in_sizes, int n_in,
                              void* d_out, int out_size) {
    (void)in_sizes; (void)n_in; (void)out_size;
    const int*   xidx = (const int*)  d_in[0];
    const float* sel  = (const float*)d_in[1];
    const int*   eidx = (const int*)  d_in[2];
    const int*   et   = (const int*)  d_in[3];
    const int*   epos = (const int*)  d_in[4];
    const float* emb  = (const float*)d_in[5];
    const float* pe   = (const float*)d_in[6];
    const float* Wg   = (const float*)d_in[7];
    const float* bg   = (const float*)d_in[8];
    const float* Wt   = (const float*)d_in[9];
    const float* bt   = (const float*)d_in[10];
    const float* Wih  = (const float*)d_in[11];
    const float* Whh  = (const float*)d_in[12];
    const float* bih  = (const float*)d_in[13];
    const float* bhh  = (const float*)d_in[14];
    const float* W1   = (const float*)d_in[15];
    const float* b1   = (const float*)d_in[16];
    const float* W2   = (const float*)d_in[17];
    const float* b2   = (const float*)d_in[18];
    float* out = (float*)d_out;
    const int* src = eidx;
    const int* dst = eidx + EE;

    const int SM_EDGE = (NT * HH * HH + NT * HH + 8 * HH) * 4;          // 202,240 B
    const int SM_GRU  = (HH * WTS + 3 * HH + 8 * HH) * 4;               // 204,288 B
    const int SM_OUT  = (2 * HH * HH + HH + 8 * 2 * HH) * 4;            // 139,776 B
    const int SM_GATE = (PDIM * HH + HH + 8 * PDIM) * 4;                //  35,328 B

    cudaFuncSetAttribute(k_edge, cudaFuncAttributeMaxDynamicSharedMemorySize, SM_EDGE);
    cudaFuncSetAttribute(k_gi,   cudaFuncAttributeMaxDynamicSharedMemorySize, SM_GRU);
    cudaFuncSetAttribute(k_gh,   cudaFuncAttributeMaxDynamicSharedMemorySize, SM_GRU);
    cudaFuncSetAttribute(k_out,  cudaFuncAttributeMaxDynamicSharedMemorySize, SM_OUT);

    k_zero_cnt<<<(NN + 255) / 256, 256>>>();
    k_h0<<<(NN * 32 + 255) / 256, 256>>>(xidx, sel, emb);
    k_deg<<<(EE + 255) / 256, 256>>>(dst);
    k_inv<<<(NN + 255) / 256, 256>>>();
    k_gate<<<1024, 256, SM_GATE>>>(epos, pe, Wg, bg);

    for (int it = 0; it < GITERS; it++) {
        int flip = it & 1;
        k_zero_agg<<<(NN * HH / 4 + 255) / 256, 256>>>();
        k_edge<<<592, 256, SM_EDGE>>>(src, dst, et, Wt, bt, flip);
        k_gi<<<304, 256, SM_GRU>>>(Wih, bih);
        k_gh<<<304, 256, SM_GRU>>>(Whh, bhh, flip);
    }
    k_out<<<304, 256, SM_OUT>>>(W1, b1, W2, b2, out);
}

// round 5
// speedup vs baseline: 1.8785x; 1.8785x over previous
#include <cuda_runtime.h>
#include <math.h>

#define NN   100000
#define EE   640000
#define HH   128
#define EMBD 96
#define SELD 32
#define PDIM 64
#define NT   3
#define GITERS 6
#define WTS  388        // padded row pitch for transposed GRU weights in smem

#define EPW  16         // edges per warp (edge kernel)
#define EWPB 8          // warps per block (edge kernel)
#define EPB  (EPW*EWPB) // 128 edges per block; type segment bases aligned to this
#define PADE (EE + NT*EPB)   // 640384 sorted+padded edge slots

#define GNW 4           // warps per block (GRU kernels)
#define GNT 8           // nodes per warp tile (GRU kernels)
#define ONW 8           // warps per block (output kernel)
#define ONT 4           // nodes per warp tile (output kernel)

// ---------------- device scratch (no allocations allowed) ----------------
__device__ float d_h0 [NN * HH];
__device__ float d_hA [NN * HH];
__device__ float d_hB [NN * HH];
__device__ float d_agg[NN * HH];
__device__ float d_gi [NN * 3 * HH];
__device__ float d_gate[PADE * HH];      // gate in SORTED edge order
__device__ float d_cnt[NN];
__device__ float d_inv[NN];
__device__ int   d_es[PADE];             // sorted src
__device__ int   d_ed[PADE];             // sorted dst (-1 = padding)
__device__ int   d_ps[PADE];             // sorted edge position
__device__ int   d_tcnt[NT];
__device__ int   d_cur[NT];
__device__ int   d_base[NT + 1];

__device__ __forceinline__ float sigf(float x) { return 1.0f / (1.0f + __expf(-x)); }

// ---- packed f32x2 helpers ----
__device__ __forceinline__ void fma2(unsigned long long& d, unsigned long long a,
                                     unsigned long long b) {
    asm("fma.rn.f32x2 %0, %1, %2, %0;" : "+l"(d) : "l"(a), "l"(b));
}
__device__ __forceinline__ unsigned long long pk2(float v) {
    unsigned long long r;
    asm("mov.b64 %0, {%1, %1};" : "=l"(r) : "f"(v));
    return r;
}
__device__ __forceinline__ float2 up2(unsigned long long v) {
    float2 r;
    asm("mov.b64 {%0, %1}, %2;" : "=f"(r.x), "=f"(r.y) : "l"(v));
    return r;
}
__device__ __forceinline__ void red4(float* p, float a, float b, float c, float d) {
    asm volatile("red.global.add.v4.f32 [%0], {%1, %2, %3, %4};"
                 :: "l"(p), "f"(a), "f"(b), "f"(c), "f"(d) : "memory");
}

// ---------------- setup kernels ----------------
__global__ void k_init_pad() {
    int i = blockIdx.x * blockDim.x + threadIdx.x;
    if (i < PADE) { d_ed[i] = -1; d_es[i] = 0; d_ps[i] = 0; }
    if (i < NT) d_tcnt[i] = 0;
}
__global__ void k_hist(const int* __restrict__ et) {
    int e = blockIdx.x * blockDim.x + threadIdx.x;
    if (e < EE) atomicAdd(&d_tcnt[et[e]], 1);
}
__global__ void k_off() {
    int b = 0;
    for (int t = 0; t < NT; t++) {
        d_base[t] = b;
        d_cur[t] = 0;
        b += ((d_tcnt[t] + EPB - 1) / EPB) * EPB;
    }
    d_base[NT] = b;
}
__global__ void k_perm(const int* __restrict__ src, const int* __restrict__ dst,
                       const int* __restrict__ et, const int* __restrict__ epos) {
    int e = blockIdx.x * blockDim.x + threadIdx.x;
    if (e >= EE) return;
    int t = et[e];
    int p = d_base[t] + atomicAdd(&d_cur[t], 1);
    d_es[p] = src[e];
    d_ed[p] = dst[e];
    d_ps[p] = epos[e];
}
__global__ void k_zero_cnt() {
    int i = blockIdx.x * blockDim.x + threadIdx.x;
    if (i < NN) d_cnt[i] = 0.0f;
}
__global__ void k_h0(const int* __restrict__ xidx, const float* __restrict__ sel,
                     const float* __restrict__ emb) {
    int t = blockIdx.x * blockDim.x + threadIdx.x;
    if (t >= NN * 32) return;
    int n = t >> 5;
    int q = (t & 31) * 4;
    float4 v;
    if (q < EMBD) v = *(const float4*)&emb[(long long)xidx[n] * EMBD + q];
    else          v = *(const float4*)&sel[n * SELD + (q - EMBD)];
    *(float4*)&d_h0[n * HH + q] = v;
    *(float4*)&d_hA[n * HH + q] = v;
}
__global__ void k_deg(const int* __restrict__ dst) {
    int e = blockIdx.x * blockDim.x + threadIdx.x;
    if (e < EE) atomicAdd(&d_cnt[dst[e]], 1.0f);
}
__global__ void k_inv() {
    int i = blockIdx.x * blockDim.x + threadIdx.x;
    if (i < NN) d_inv[i] = 1.0f / fmaxf(d_cnt[i], 1.0f);
}
__global__ void k_zero_agg() {
    int i = blockIdx.x * blockDim.x + threadIdx.x;
    if (i < NN * HH / 4) ((float4*)d_agg)[i] = make_float4(0.f, 0.f, 0.f, 0.f);
}

// gate[p,:] = 2*sigmoid(pe[pos_s[p]] @ Wg + bg), 16 edges/warp, dup staging, FFMA2
__global__ __launch_bounds__(256) void k_gate(const float* __restrict__ pe,
                                              const float* __restrict__ Wg,
                                              const float* __restrict__ bg) {
    extern __shared__ float sm[];
    float* Ws = sm;                      // 64*128
    float* Xs = sm + PDIM * HH;          // 8 warps * 16 edges * 128 (dup of 64)
    for (int i = threadIdx.x; i < PDIM * HH / 4; i += 256)
        ((float4*)Ws)[i] = ((const float4*)Wg)[i];
    int lane = threadIdx.x & 31, w = threadIdx.x >> 5;
    float4 bb = *(const float4*)&bg[4 * lane];
    __syncthreads();
    float* X = Xs + w * (EPW * 2 * PDIM);
    int e0 = blockIdx.x * EPB + w * EPW;
    #pragma unroll
    for (int i = 0; i < EPW; i++) {
        int pos = d_ps[e0 + i];
        float2 f = *(const float2*)&pe[pos * PDIM + 2 * lane];
        *(float4*)&X[i * 2 * PDIM + 4 * lane] = make_float4(f.x, f.x, f.y, f.y);
    }
    __syncwarp();
    unsigned long long acc[EPW][2];
    #pragma unroll
    for (int i = 0; i < EPW; i++) { acc[i][0] = 0ull; acc[i][1] = 0ull; }
    #pragma unroll 2
    for (int k = 0; k < PDIM; k += 2) {
        ulonglong2 wa = *(const ulonglong2*)&Ws[(k + 0) * HH + 4 * lane];
        ulonglong2 wb = *(const ulonglong2*)&Ws[(k + 1) * HH + 4 * lane];
        #pragma unroll
        for (int i = 0; i < EPW; i++) {
            ulonglong2 xp = *(const ulonglong2*)&X[i * 2 * PDIM + 2 * k];
            fma2(acc[i][0], xp.x, wa.x); fma2(acc[i][1], xp.x, wa.y);
            fma2(acc[i][0], xp.y, wb.x); fma2(acc[i][1], xp.y, wb.y);
        }
    }
    #pragma unroll
    for (int i = 0; i < EPW; i++) {
        float2 p0 = up2(acc[i][0]), p1 = up2(acc[i][1]);
        float4 g;
        g.x = 2.0f * sigf(p0.x + bb.x);
        g.y = 2.0f * sigf(p0.y + bb.y);
        g.z = 2.0f * sigf(p1.x + bb.z);
        g.w = 2.0f * sigf(p1.y + bb.w);
        *(float4*)&d_gate[(e0 + i) * HH + 4 * lane] = g;
    }
}

// edge phase: 16 edges/warp (all same type per block via sort), dup staging, FFMA2,
// vector red.global.add.v4 scatter with bias+1/deg folded.
__global__ __launch_bounds__(256) void k_edge(const float* __restrict__ Wt,
                                              const float* __restrict__ bt,
                                              int flip) {
    extern __shared__ float sm[];
    float* Ws = sm;                      // 128*128
    float* Xs = sm + HH * HH;            // 8 warps * 16 edges * 256 (dup of 128)
    const float* __restrict__ h = flip ? d_hB : d_hA;
    int start = blockIdx.x * EPB;
    int t = (start >= d_base[1]) + (start >= d_base[2]);
    const float4* wg = (const float4*)(Wt + t * HH * HH);
    for (int i = threadIdx.x; i < HH * HH / 4; i += 256) ((float4*)Ws)[i] = wg[i];
    int lane = threadIdx.x & 31, w = threadIdx.x >> 5;
    float4 bb = *(const float4*)&bt[t * HH + 4 * lane];
    __syncthreads();
    float* X = Xs + w * (EPW * 2 * HH);
    int e0 = start + w * EPW;
    #pragma unroll
    for (int i = 0; i < EPW; i++) {
        int s = d_es[e0 + i];
        float4 hv = *(const float4*)&h[s * HH + 4 * lane];
        float4 gv = *(const float4*)&d_gate[(e0 + i) * HH + 4 * lane];
        float x0 = hv.x * gv.x, x1 = hv.y * gv.y, x2 = hv.z * gv.z, x3 = hv.w * gv.w;
        float* xr = X + i * 2 * HH + 8 * lane;
        *(float4*)(xr)     = make_float4(x0, x0, x1, x1);
        *(float4*)(xr + 4) = make_float4(x2, x2, x3, x3);
    }
    __syncwarp();
    unsigned long long acc[EPW][2];
    #pragma unroll
    for (int i = 0; i < EPW; i++) { acc[i][0] = 0ull; acc[i][1] = 0ull; }
    #pragma unroll 2
    for (int k = 0; k < HH; k += 2) {
        ulonglong2 wa = *(const ulonglong2*)&Ws[(k + 0) * HH + 4 * lane];
        ulonglong2 wb = *(const ulonglong2*)&Ws[(k + 1) * HH + 4 * lane];
        #pragma unroll
        for (int i = 0; i < EPW; i++) {
            ulonglong2 xp = *(const ulonglong2*)&X[i * 2 * HH + 2 * k];
            fma2(acc[i][0], xp.x, wa.x); fma2(acc[i][1], xp.x, wa.y);
            fma2(acc[i][0], xp.y, wb.x); fma2(acc[i][1], xp.y, wb.y);
        }
    }
    #pragma unroll
    for (int i = 0; i < EPW; i++) {
        int d = d_ed[e0 + i];
        if (d >= 0) {
            float invd = d_inv[d];
            float2 p0 = up2(acc[i][0]), p1 = up2(acc[i][1]);
            red4(&d_agg[d * HH + 4 * lane],
                 (p0.x + bb.x) * invd, (p0.y + bb.y) * invd,
                 (p1.x + bb.z) * invd, (p1.y + bb.w) * invd);
        }
    }
}

// gi = agg @ W_ih^T + b_ih, 8 nodes/warp, weights transposed in smem, FFMA2
__global__ __launch_bounds__(128) void k_gi(const float* __restrict__ Wih,
                                            const float* __restrict__ bih) {
    extern __shared__ float sm[];
    float* wt = sm;                      // [128][WTS]
    float* Xs = wt + HH * WTS;           // 4 warps * 8 nodes * 128
    for (int i = threadIdx.x; i < 3 * HH * HH; i += 128) {
        int j = i >> 7, k = i & 127;
        wt[k * WTS + j] = Wih[i];
    }
    int lane = threadIdx.x & 31, w = threadIdx.x >> 5;
    float4 b0 = *(const float4*)&bih[4 * lane];
    float4 b1 = *(const float4*)&bih[128 + 4 * lane];
    float4 b2 = *(const float4*)&bih[256 + 4 * lane];
    __syncthreads();
    float* X = Xs + w * (GNT * HH);
    int gw = blockIdx.x * GNW + w;
    for (int n0 = gw * GNT; n0 < NN; n0 += 148 * GNW * GNT) {
        #pragma unroll
        for (int i = 0; i < GNT; i++)
            *(float4*)&X[i * HH + 4 * lane] = *(const float4*)&d_agg[(n0 + i) * HH + 4 * lane];
        __syncwarp();
        unsigned long long acc[GNT][6];
        #pragma unroll
        for (int i = 0; i < GNT; i++)
            #pragma unroll
            for (int q = 0; q < 6; q++) acc[i][q] = 0ull;
        #pragma unroll 2
        for (int k = 0; k < HH; k++) {
            const float* row = &wt[k * WTS];
            ulonglong2 w0 = *(const ulonglong2*)&row[      4 * lane];
            ulonglong2 w1 = *(const ulonglong2*)&row[128 + 4 * lane];
            ulonglong2 w2 = *(const ulonglong2*)&row[256 + 4 * lane];
            #pragma unroll
            for (int i = 0; i < GNT; i++) {
                unsigned long long xp = pk2(X[i * HH + k]);
                fma2(acc[i][0], xp, w0.x); fma2(acc[i][1], xp, w0.y);
                fma2(acc[i][2], xp, w1.x); fma2(acc[i][3], xp, w1.y);
                fma2(acc[i][4], xp, w2.x); fma2(acc[i][5], xp, w2.y);
            }
        }
        #pragma unroll
        for (int i = 0; i < GNT; i++) {
            float* gp = &d_gi[(n0 + i) * 3 * HH];
            float2 q0 = up2(acc[i][0]), q1 = up2(acc[i][1]), q2 = up2(acc[i][2]);
            float2 q3 = up2(acc[i][3]), q4 = up2(acc[i][4]), q5 = up2(acc[i][5]);
            *(float4*)&gp[      4 * lane] = make_float4(q0.x + b0.x, q0.y + b0.y, q1.x + b0.z, q1.y + b0.w);
            *(float4*)&gp[128 + 4 * lane] = make_float4(q2.x + b1.x, q2.y + b1.y, q3.x + b1.z, q3.y + b1.w);
            *(float4*)&gp[256 + 4 * lane] = make_float4(q4.x + b2.x, q4.y + b2.y, q5.x + b2.z, q5.y + b2.w);
        }
        __syncwarp();
    }
}

// gh = h @ W_hh^T + b_hh, fused GRU combine -> h_next. Same tiling as k_gi.
__global__ __launch_bounds__(128) void k_gh(const float* __restrict__ Whh,
                                            const float* __restrict__ bhh,
                                            int flip) {
    extern __shared__ float sm[];
    float* wt = sm;
    float* Xs = wt + HH * WTS;
    for (int i = threadIdx.x; i < 3 * HH * HH; i += 128) {
        int j = i >> 7, k = i & 127;
        wt[k * WTS + j] = Whh[i];
    }
    int lane = threadIdx.x & 31, w = threadIdx.x >> 5;
    float4 b0 = *(const float4*)&bhh[4 * lane];
    float4 b1 = *(const float4*)&bhh[128 + 4 * lane];
    float4 b2 = *(const float4*)&bhh[256 + 4 * lane];
    __syncthreads();
    const float* __restrict__ h = flip ? d_hB : d_hA;
    float* __restrict__ hn      = flip ? d_hA : d_hB;
    float* X = Xs + w * (GNT * HH);
    int gw = blockIdx.x * GNW + w;
    for (int n0 = gw * GNT; n0 < NN; n0 += 148 * GNW * GNT) {
        #pragma unroll
        for (int i = 0; i < GNT; i++)
            *(float4*)&X[i * HH + 4 * lane] = *(const float4*)&h[(n0 + i) * HH + 4 * lane];
        __syncwarp();
        unsigned long long acc[GNT][6];
        #pragma unroll
        for (int i = 0; i < GNT; i++)
            #pragma unroll
            for (int q = 0; q < 6; q++) acc[i][q] = 0ull;
        #pragma unroll 2
        for (int k = 0; k < HH; k++) {
            const float* row = &wt[k * WTS];
            ulonglong2 w0 = *(const ulonglong2*)&row[      4 * lane];
            ulonglong2 w1 = *(const ulonglong2*)&row[128 + 4 * lane];
            ulonglong2 w2 = *(const ulonglong2*)&row[256 + 4 * lane];
            #pragma unroll
            for (int i = 0; i < GNT; i++) {
                unsigned long long xp = pk2(X[i * HH + k]);
                fma2(acc[i][0], xp, w0.x); fma2(acc[i][1], xp, w0.y);
                fma2(acc[i][2], xp, w1.x); fma2(acc[i][3], xp, w1.y);
                fma2(acc[i][4], xp, w2.x); fma2(acc[i][5], xp, w2.y);
            }
        }
        #pragma unroll
        for (int i = 0; i < GNT; i++) {
            float2 q0 = up2(acc[i][0]), q1 = up2(acc[i][1]), q2 = up2(acc[i][2]);
            float2 q3 = up2(acc[i][3]), q4 = up2(acc[i][4]), q5 = up2(acc[i][5]);
            float hr0 = q0.x + b0.x, hr1 = q0.y + b0.y, hr2 = q1.x + b0.z, hr3 = q1.y + b0.w;
            float hz0 = q2.x + b1.x, hz1 = q2.y + b1.y, hz2 = q3.x + b1.z, hz3 = q3.y + b1.w;
            float hn0 = q4.x + b2.x, hn1 = q4.y + b2.y, hn2 = q5.x + b2.z, hn3 = q5.y + b2.w;
            const float* gp = &d_gi[(n0 + i) * 3 * HH];
            float4 g0 = *(const float4*)&gp[      4 * lane];
            float4 g1 = *(const float4*)&gp[128 + 4 * lane];
            float4 g2 = *(const float4*)&gp[256 + 4 * lane];
            float4 hh = *(const float4*)&h[(n0 + i) * HH + 4 * lane];
            float4 o;
            { float r = sigf(g0.x + hr0); float z = sigf(g1.x + hz0);
              float nv = tanhf(g2.x + r * hn0); o.x = (1.0f - z) * nv + z * hh.x; }
            { float r = sigf(g0.y + hr1); float z = sigf(g1.y + hz1);
              float nv = tanhf(g2.y + r * hn1); o.y = (1.0f - z) * nv + z * hh.y; }
            { float r = sigf(g0.z + hr2); float z = sigf(g1.z + hz2);
              float nv = tanhf(g2.z + r * hn2); o.z = (1.0f - z) * nv + z * hh.z; }
            { float r = sigf(g0.w + hr3); float z = sigf(g1.w + hz3);
              float nv = tanhf(g2.w + r * hn3); o.w = (1.0f - z) * nv + z * hh.w; }
            *(float4*)&hn[(n0 + i) * HH + 4 * lane] = o;
        }
        __syncwarp();
    }
}

// logits = relu([h, h0] @ W1 + b1) @ W2 + b2, 4 nodes/warp, dup staging, FFMA2
__global__ __launch_bounds__(256) void k_out(const float* __restrict__ W1,
                                             const float* __restrict__ b1,
                                             const float* __restrict__ W2,
                                             const float* __restrict__ b2,
                                             float* __restrict__ out) {
    extern __shared__ float sm[];
    float* Ws = sm;                      // 256*128
    float* Xs = sm + 2 * HH * HH;        // 8 warps * 4 nodes * 512 (dup of 256)
    for (int i = threadIdx.x; i < 2 * HH * HH / 4; i += 256)
        ((float4*)Ws)[i] = ((const float4*)W1)[i];
    int lane = threadIdx.x & 31, w = threadIdx.x >> 5;
    float4 bb = *(const float4*)&b1[4 * lane];
    float4 w2v = *(const float4*)&W2[4 * lane];
    float b2v = b2[0];
    __syncthreads();
    float* X = Xs + w * (ONT * 2 * 2 * HH);
    int gw = blockIdx.x * ONW + w;
    for (int n0 = gw * ONT; n0 < NN; n0 += 148 * ONW * ONT) {
        #pragma unroll
        for (int i = 0; i < ONT; i++) {
            float4 a = *(const float4*)&d_hA[(n0 + i) * HH + 4 * lane];
            float4 c = *(const float4*)&d_h0[(n0 + i) * HH + 4 * lane];
            float* xr = X + i * 512;
            *(float4*)(xr + 8 * lane)           = make_float4(a.x, a.x, a.y, a.y);
            *(float4*)(xr + 8 * lane + 4)       = make_float4(a.z, a.z, a.w, a.w);
            *(float4*)(xr + 256 + 8 * lane)     = make_float4(c.x, c.x, c.y, c.y);
            *(float4*)(xr + 256 + 8 * lane + 4) = make_float4(c.z, c.z, c.w, c.w);
        }
        __syncwarp();
        unsigned long long acc[ONT][2];
        #pragma unroll
        for (int i = 0; i < ONT; i++) { acc[i][0] = 0ull; acc[i][1] = 0ull; }
        #pragma unroll 2
        for (int k = 0; k < 2 * HH; k += 2) {
            ulonglong2 wa = *(const ulonglong2*)&Ws[(k + 0) * HH + 4 * lane];
            ulonglong2 wb = *(const ulonglong2*)&Ws[(k + 1) * HH + 4 * lane];
            #pragma unroll
            for (int i = 0; i < ONT; i++) {
                ulonglong2 xp = *(const ulonglong2*)&X[i * 512 + 2 * k];
                fma2(acc[i][0], xp.x, wa.x); fma2(acc[i][1], xp.x, wa.y);
                fma2(acc[i][0], xp.y, wb.x); fma2(acc[i][1], xp.y, wb.y);
            }
        }
        #pragma unroll
        for (int i = 0; i < ONT; i++) {
            float2 p0 = up2(acc[i][0]), p1 = up2(acc[i][1]);
            float r0 = fmaxf(p0.x + bb.x, 0.f), r1 = fmaxf(p0.y + bb.y, 0.f);
            float r2 = fmaxf(p1.x + bb.z, 0.f), r3 = fmaxf(p1.y + bb.w, 0.f);
            float p = r0 * w2v.x + r1 * w2v.y + r2 * w2v.z + r3 * w2v.w;
            #pragma unroll
            for (int o = 16; o > 0; o >>= 1) p += __shfl_xor_sync(0xFFFFFFFFu, p, o);
            if (lane == 0) out[n0 + i] = p + b2v;
        }
        __syncwarp();
    }
}

// ---------------- launch ----------------
extern "C" void kernel_launch(void* const* d_in, const int* in_sizes, int n_in,
                              void* d_out, int out_size) {
    (void)in_sizes; (void)n_in; (void)out_size;
    const int*   xidx = (const int*)  d_in[0];
    const float* sel  = (const float*)d_in[1];
    const int*   eidx = (const int*)  d_in[2];
    const int*   et   = (const int*)  d_in[3];
    const int*   epos = (const int*)  d_in[4];
    const float* emb  = (const float*)d_in[5];
    const float* pe   = (const float*)d_in[6];
    const float* Wg   = (const float*)d_in[7];
    const float* bg   = (const float*)d_in[8];
    const float* Wt   = (const float*)d_in[9];
    const float* bt   = (const float*)d_in[10];
    const float* Wih  = (const float*)d_in[11];
    const float* Whh  = (const float*)d_in[12];
    const float* bih  = (const float*)d_in[13];
    const float* bhh  = (const float*)d_in[14];
    const float* W1   = (const float*)d_in[15];
    const float* b1   = (const float*)d_in[16];
    const float* W2   = (const float*)d_in[17];
    const float* b2   = (const float*)d_in[18];
    float* out = (float*)d_out;
    const int* src = eidx;
    const int* dst = eidx + EE;

    const int SM_EDGE = (HH * HH + EWPB * EPW * 2 * HH) * 4;        // 196,608
    const int SM_GRU  = (HH * WTS + GNW * GNT * HH) * 4;            // 215,040
    const int SM_OUT  = (2 * HH * HH + ONW * ONT * 2 * 2 * HH) * 4; // 196,608
    const int SM_GATE = (PDIM * HH + EWPB * EPW * 2 * PDIM) * 4;    //  98,304

    cudaFuncSetAttribute(k_edge, cudaFuncAttributeMaxDynamicSharedMemorySize, SM_EDGE);
    cudaFuncSetAttribute(k_gi,   cudaFuncAttributeMaxDynamicSharedMemorySize, SM_GRU);
    cudaFuncSetAttribute(k_gh,   cudaFuncAttributeMaxDynamicSharedMemorySize, SM_GRU);
    cudaFuncSetAttribute(k_out,  cudaFuncAttributeMaxDynamicSharedMemorySize, SM_OUT);
    cudaFuncSetAttribute(k_gate, cudaFuncAttributeMaxDynamicSharedMemorySize, SM_GATE);

    // setup: type sort + degrees + h0 + gate (all once per replay)
    k_init_pad<<<(PADE + 255) / 256, 256>>>();
    k_hist<<<(EE + 255) / 256, 256>>>(et);
    k_off<<<1, 1>>>();
    k_perm<<<(EE + 255) / 256, 256>>>(src, dst, et, epos);
    k_zero_cnt<<<(NN + 255) / 256, 256>>>();
    k_h0<<<(NN * 32 + 255) / 256, 256>>>(xidx, sel, emb);
    k_deg<<<(EE + 255) / 256, 256>>>(dst);
    k_inv<<<(NN + 255) / 256, 256>>>();
    k_gate<<<PADE / EPB, 256, SM_GATE>>>(pe, Wg, bg);

    for (int it = 0; it < GITERS; it++) {
        int flip = it & 1;
        k_zero_agg<<<(NN * HH / 4 + 255) / 256, 256>>>();
        k_edge<<<PADE / EPB, 256, SM_EDGE>>>(Wt, bt, flip);
        k_gi<<<148, 128, SM_GRU>>>(Wih, bih);
        k_gh<<<148, 128, SM_GRU>>>(Whh, bhh, flip);
    }
    k_out<<<148, 256, SM_OUT>>>(W1, b1, W2, b2, out);
}

// round 7
// speedup vs baseline: 2.0760x; 1.1051x over previous
#include <cuda_runtime.h>
#include <math.h>

#define NN   100000
#define EE   640000
#define HH   128
#define EMBD 96
#define SELD 32
#define PDIM 64
#define NPOS 513        // MAXPOS+1
#define NT   3
#define GITERS 6
#define WTS  388        // padded row pitch for transposed GRU weights in smem

#define EPW  16         // edges per warp (edge kernel)
#define EWPB 8          // warps per block (edge kernel)
#define EPB  (EPW*EWPB) // 128 edges per block; type segment bases aligned to this
#define PADE (EE + NT*EPB)   // 640384 sorted+padded edge slots

#define GNW 4           // warps per block (GRU kernels)
#define GNT 8           // nodes per warp tile (GRU kernels)
#define ONW 8           // warps per block (output kernel)
#define ONT 4           // nodes per warp tile (output kernel)

// ---------------- device scratch (no allocations allowed) ----------------
__device__ float d_h0 [NN * HH];
__device__ float d_hA [NN * HH];
__device__ float d_hB [NN * HH];
__device__ float d_agg[NN * HH];
__device__ float d_gi [NN * 3 * HH];
__device__ float d_gtab[NPOS * HH];      // gate table: 513 x 128 (262 KB, L2-resident)
__device__ float d_cnt[NN];
__device__ float d_inv[NN];
__device__ int   d_es[PADE];             // sorted src
__device__ int   d_ed[PADE];             // sorted dst (-1 = padding)
__device__ int   d_ps[PADE];             // sorted edge position
__device__ int   d_tcnt[NT];
__device__ int   d_cur[NT];
__device__ int   d_base[NT + 1];

__device__ __forceinline__ float sigf(float x) { return 1.0f / (1.0f + __expf(-x)); }

// ---- packed f32x2 helpers ----
__device__ __forceinline__ void fma2(unsigned long long& d, unsigned long long a,
                                     unsigned long long b) {
    asm("fma.rn.f32x2 %0, %1, %2, %0;" : "+l"(d) : "l"(a), "l"(b));
}
__device__ __forceinline__ unsigned long long pk2(float v) {
    unsigned long long r;
    asm("mov.b64 %0, {%1, %1};" : "=l"(r) : "f"(v));
    return r;
}
__device__ __forceinline__ float2 up2(unsigned long long v) {
    float2 r;
    asm("mov.b64 {%0, %1}, %2;" : "=f"(r.x), "=f"(r.y) : "l"(v));
    return r;
}
__device__ __forceinline__ void red4(float* p, float a, float b, float c, float d) {
    asm volatile("red.global.add.v4.f32 [%0], {%1, %2, %3, %4};"
                 :: "l"(p), "f"(a), "f"(b), "f"(c), "f"(d) : "memory");
}

// ---------------- setup kernels ----------------
__global__ void k_init_pad() {
    int i = blockIdx.x * blockDim.x + threadIdx.x;
    if (i < PADE) { d_ed[i] = -1; d_es[i] = 0; d_ps[i] = 0; }
    if (i < NT) { d_tcnt[i] = 0; d_cur[i] = 0; }
}
__global__ void k_hist(const int* __restrict__ et) {
    __shared__ int sc[NT];
    if (threadIdx.x < NT) sc[threadIdx.x] = 0;
    __syncthreads();
    int e = blockIdx.x * blockDim.x + threadIdx.x;
    if (e < EE) atomicAdd(&sc[et[e]], 1);
    __syncthreads();
    if (threadIdx.x < NT) atomicAdd(&d_tcnt[threadIdx.x], sc[threadIdx.x]);
}
__global__ void k_off() {
    int b = 0;
    for (int t = 0; t < NT; t++) {
        d_base[t] = b;
        b += ((d_tcnt[t] + EPB - 1) / EPB) * EPB;
    }
    d_base[NT] = b;
}
// block-aggregated counting-sort scatter: 3 global atomics per block
__global__ void k_perm(const int* __restrict__ src, const int* __restrict__ dst,
                       const int* __restrict__ et, const int* __restrict__ epos) {
    __shared__ int s_cnt[NT], s_base[NT];
    if (threadIdx.x < NT) s_cnt[threadIdx.x] = 0;
    __syncthreads();
    int e = blockIdx.x * blockDim.x + threadIdx.x;
    int t = 0, lr = 0;
    if (e < EE) { t = et[e]; lr = atomicAdd(&s_cnt[t], 1); }
    __syncthreads();
    if (threadIdx.x < NT) s_base[threadIdx.x] = atomicAdd(&d_cur[threadIdx.x], s_cnt[threadIdx.x]);
    __syncthreads();
    if (e < EE) {
        int p = d_base[t] + s_base[t] + lr;
        d_es[p] = src[e];
        d_ed[p] = dst[e];
        d_ps[p] = epos[e];
    }
}
__global__ void k_zero_cnt() {
    int i = blockIdx.x * blockDim.x + threadIdx.x;
    if (i < NN) d_cnt[i] = 0.0f;
}
__global__ void k_h0(const int* __restrict__ xidx, const float* __restrict__ sel,
                     const float* __restrict__ emb) {
    int t = blockIdx.x * blockDim.x + threadIdx.x;
    if (t >= NN * 32) return;
    int n = t >> 5;
    int q = (t & 31) * 4;
    float4 v;
    if (q < EMBD) v = *(const float4*)&emb[(long long)xidx[n] * EMBD + q];
    else          v = *(const float4*)&sel[n * SELD + (q - EMBD)];
    *(float4*)&d_h0[n * HH + q] = v;
    *(float4*)&d_hA[n * HH + q] = v;
}
__global__ void k_deg(const int* __restrict__ dst) {
    int e = blockIdx.x * blockDim.x + threadIdx.x;
    if (e < EE) atomicAdd(&d_cnt[dst[e]], 1.0f);
}
__global__ void k_inv() {
    int i = blockIdx.x * blockDim.x + threadIdx.x;
    if (i < NN) d_inv[i] = 1.0f / fmaxf(d_cnt[i], 1.0f);
}
__global__ void k_zero_agg() {
    int i = blockIdx.x * blockDim.x + threadIdx.x;
    if (i < NN * HH / 4) ((float4*)d_agg)[i] = make_float4(0.f, 0.f, 0.f, 0.f);
}

// gate table: d_gtab[p,:] = 2*sigmoid(pe[p] @ Wg + bg), one block per position
__global__ __launch_bounds__(128) void k_gtab(const float* __restrict__ pe,
                                              const float* __restrict__ Wg,
                                              const float* __restrict__ bg) {
    __shared__ float ps[PDIM];
    int p = blockIdx.x;
    if (threadIdx.x < PDIM) ps[threadIdx.x] = pe[p * PDIM + threadIdx.x];
    __syncthreads();
    int j = threadIdx.x;
    float a = 0.0f;
    #pragma unroll 8
    for (int k = 0; k < PDIM; k++) a += ps[k] * Wg[k * HH + j];
    d_gtab[p * HH + j] = 2.0f * sigf(a + bg[j]);
}

// edge phase: 16 edges/warp (single type per block via sort), dup staging,
// broadcast LDS.64 X reads, FFMA2, vector red.global.add.v4 scatter.
__global__ __launch_bounds__(256) void k_edge(const float* __restrict__ Wt,
                                              const float* __restrict__ bt,
                                              int flip) {
    extern __shared__ float sm[];
    float* Ws = sm;                      // 128*128
    float* Xs = sm + HH * HH;            // 8 warps * 16 edges * 256 (dup of 128)
    const float* __restrict__ h = flip ? d_hB : d_hA;
    int start = blockIdx.x * EPB;
    int t = (start >= d_base[1]) + (start >= d_base[2]);
    const float4* wg = (const float4*)(Wt + t * HH * HH);
    for (int i = threadIdx.x; i < HH * HH / 4; i += 256) ((float4*)Ws)[i] = wg[i];
    int lane = threadIdx.x & 31, w = threadIdx.x >> 5;
    float4 bb = *(const float4*)&bt[t * HH + 4 * lane];
    __syncthreads();
    float* X = Xs + w * (EPW * 2 * HH);
    int e0 = start + w * EPW;
    #pragma unroll
    for (int i = 0; i < EPW; i++) {
        int s = d_es[e0 + i];
        int p = d_ps[e0 + i];
        float4 hv = *(const float4*)&h[s * HH + 4 * lane];
        float4 gv = *(const float4*)&d_gtab[p * HH + 4 * lane];
        float x0 = hv.x * gv.x, x1 = hv.y * gv.y, x2 = hv.z * gv.z, x3 = hv.w * gv.w;
        float* xr = X + i * 2 * HH + 8 * lane;
        *(float4*)(xr)     = make_float4(x0, x0, x1, x1);
        *(float4*)(xr + 4) = make_float4(x2, x2, x3, x3);
    }
    __syncwarp();
    unsigned long long acc[EPW][2];
    #pragma unroll
    for (int i = 0; i < EPW; i++) { acc[i][0] = 0ull; acc[i][1] = 0ull; }
    #pragma unroll 4
    for (int k = 0; k < HH; k++) {
        ulonglong2 wv = *(const ulonglong2*)&Ws[k * HH + 4 * lane];
        #pragma unroll
        for (int i = 0; i < EPW; i++) {
            unsigned long long xk = *(const unsigned long long*)&X[i * 2 * HH + 2 * k];
            fma2(acc[i][0], xk, wv.x);
            fma2(acc[i][1], xk, wv.y);
        }
    }
    #pragma unroll
    for (int i = 0; i < EPW; i++) {
        int d = d_ed[e0 + i];
        if (d >= 0) {
            float invd = d_inv[d];
            float2 p0 = up2(acc[i][0]), p1 = up2(acc[i][1]);
            red4(&d_agg[d * HH + 4 * lane],
                 (p0.x + bb.x) * invd, (p0.y + bb.y) * invd,
                 (p1.x + bb.z) * invd, (p1.y + bb.w) * invd);
        }
    }
}

// gi = agg @ W_ih^T + b_ih, 8 nodes/warp, weights transposed in smem, FFMA2
__global__ __launch_bounds__(128) void k_gi(const float* __restrict__ Wih,
                                            const float* __restrict__ bih) {
    extern __shared__ float sm[];
    float* wt = sm;                      // [128][WTS]
    float* Xs = wt + HH * WTS;           // 4 warps * 8 nodes * 128
    for (int i = threadIdx.x; i < 3 * HH * HH; i += 128) {
        int j = i >> 7, k = i & 127;
        wt[k * WTS + j] = Wih[i];
    }
    int lane = threadIdx.x & 31, w = threadIdx.x >> 5;
    float4 b0 = *(const float4*)&bih[4 * lane];
    float4 b1 = *(const float4*)&bih[128 + 4 * lane];
    float4 b2 = *(const float4*)&bih[256 + 4 * lane];
    __syncthreads();
    float* X = Xs + w * (GNT * HH);
    int gw = blockIdx.x * GNW + w;
    for (int n0 = gw * GNT; n0 < NN; n0 += 148 * GNW * GNT) {
        #pragma unroll
        for (int i = 0; i < GNT; i++)
            *(float4*)&X[i * HH + 4 * lane] = *(const float4*)&d_agg[(n0 + i) * HH + 4 * lane];
        __syncwarp();
        unsigned long long acc[GNT][6];
        #pragma unroll
        for (int i = 0; i < GNT; i++)
            #pragma unroll
            for (int q = 0; q < 6; q++) acc[i][q] = 0ull;
        #pragma unroll 2
        for (int k = 0; k < HH; k++) {
            const float* row = &wt[k * WTS];
            ulonglong2 w0 = *(const ulonglong2*)&row[      4 * lane];
            ulonglong2 w1 = *(const ulonglong2*)&row[128 + 4 * lane];
            ulonglong2 w2 = *(const ulonglong2*)&row[256 + 4 * lane];
            #pragma unroll
            for (int i = 0; i < GNT; i++) {
                unsigned long long xp = pk2(X[i * HH + k]);
                fma2(acc[i][0], xp, w0.x); fma2(acc[i][1], xp, w0.y);
                fma2(acc[i][2], xp, w1.x); fma2(acc[i][3], xp, w1.y);
                fma2(acc[i][4], xp, w2.x); fma2(acc[i][5], xp, w2.y);
            }
        }
        #pragma unroll
        for (int i = 0; i < GNT; i++) {
            float* gp = &d_gi[(n0 + i) * 3 * HH];
            float2 q0 = up2(acc[i][0]), q1 = up2(acc[i][1]), q2 = up2(acc[i][2]);
            float2 q3 = up2(acc[i][3]), q4 = up2(acc[i][4]), q5 = up2(acc[i][5]);
            *(float4*)&gp[      4 * lane] = make_float4(q0.x + b0.x, q0.y + b0.y, q1.x + b0.z, q1.y + b0.w);
            *(float4*)&gp[128 + 4 * lane] = make_float4(q2.x + b1.x, q2.y + b1.y, q3.x + b1.z, q3.y + b1.w);
            *(float4*)&gp[256 + 4 * lane] = make_float4(q4.x + b2.x, q4.y + b2.y, q5.x + b2.z, q5.y + b2.w);
        }
        __syncwarp();
    }
}

// gh = h @ W_hh^T + b_hh, fused GRU combine -> h_next. Same tiling as k_gi.
__global__ __launch_bounds__(128) void k_gh(const float* __restrict__ Whh,
                                            const float* __restrict__ bhh,
                                            int flip) {
    extern __shared__ float sm[];
    float* wt = sm;
    float* Xs = wt + HH * WTS;
    for (int i = threadIdx.x; i < 3 * HH * HH; i += 128) {
        int j = i >> 7, k = i & 127;
        wt[k * WTS + j] = Whh[i];
    }
    int lane = threadIdx.x & 31, w = threadIdx.x >> 5;
    float4 b0 = *(const float4*)&bhh[4 * lane];
    float4 b1 = *(const float4*)&bhh[128 + 4 * lane];
    float4 b2 = *(const float4*)&bhh[256 + 4 * lane];
    __syncthreads();
    const float* __restrict__ h = flip ? d_hB : d_hA;
    float* __restrict__ hn      = flip ? d_hA : d_hB;
    float* X = Xs + w * (GNT * HH);
    int gw = blockIdx.x * GNW + w;
    for (int n0 = gw * GNT; n0 < NN; n0 += 148 * GNW * GNT) {
        #pragma unroll
        for (int i = 0; i < GNT; i++)
            *(float4*)&X[i * HH + 4 * lane] = *(const float4*)&h[(n0 + i) * HH + 4 * lane];
        __syncwarp();
        unsigned long long acc[GNT][6];
        #pragma unroll
        for (int i = 0; i < GNT; i++)
            #pragma unroll
            for (int q = 0; q < 6; q++) acc[i][q] = 0ull;
        #pragma unroll 2
        for (int k = 0; k < HH; k++) {
            const float* row = &wt[k * WTS];
            ulonglong2 w0 = *(const ulonglong2*)&row[      4 * lane];
            ulonglong2 w1 = *(const ulonglong2*)&row[128 + 4 * lane];
            ulonglong2 w2 = *(const ulonglong2*)&row[256 + 4 * lane];
            #pragma unroll
            for (int i = 0; i < GNT; i++) {
                unsigned long long xp = pk2(X[i * HH + k]);
                fma2(acc[i][0], xp, w0.x); fma2(acc[i][1], xp, w0.y);
                fma2(acc[i][2], xp, w1.x); fma2(acc[i][3], xp, w1.y);
                fma2(acc[i][4], xp, w2.x); fma2(acc[i][5], xp, w2.y);
            }
        }
        #pragma unroll
        for (int i = 0; i < GNT; i++) {
            float2 q0 = up2(acc[i][0]), q1 = up2(acc[i][1]), q2 = up2(acc[i][2]);
            float2 q3 = up2(acc[i][3]), q4 = up2(acc[i][4]), q5 = up2(acc[i][5]);
            float hr0 = q0.x + b0.x, hr1 = q0.y + b0.y, hr2 = q1.x + b0.z, hr3 = q1.y + b0.w;
            float hz0 = q2.x + b1.x, hz1 = q2.y + b1.y, hz2 = q3.x + b1.z, hz3 = q3.y + b1.w;
            float hn0 = q4.x + b2.x, hn1 = q4.y + b2.y, hn2 = q5.x + b2.z, hn3 = q5.y + b2.w;
            const float* gp = &d_gi[(n0 + i) * 3 * HH];
            float4 g0 = *(const float4*)&gp[      4 * lane];
            float4 g1 = *(const float4*)&gp[128 + 4 * lane];
            float4 g2 = *(const float4*)&gp[256 + 4 * lane];
            float4 hh = *(const float4*)&h[(n0 + i) * HH + 4 * lane];
            float4 o;
            { float r = sigf(g0.x + hr0); float z = sigf(g1.x + hz0);
              float nv = tanhf(g2.x + r * hn0); o.x = (1.0f - z) * nv + z * hh.x; }
            { float r = sigf(g0.y + hr1); float z = sigf(g1.y + hz1);
              float nv = tanhf(g2.y + r * hn1); o.y = (1.0f - z) * nv + z * hh.y; }
            { float r = sigf(g0.z + hr2); float z = sigf(g1.z + hz2);
              float nv = tanhf(g2.z + r * hn2); o.z = (1.0f - z) * nv + z * hh.z; }
            { float r = sigf(g0.w + hr3); float z = sigf(g1.w + hz3);
              float nv = tanhf(g2.w + r * hn3); o.w = (1.0f - z) * nv + z * hh.w; }
            *(float4*)&hn[(n0 + i) * HH + 4 * lane] = o;
        }
        __syncwarp();
    }
}

// logits = relu([h, h0] @ W1 + b1) @ W2 + b2, 4 nodes/warp, broadcast X, FFMA2
__global__ __launch_bounds__(256) void k_out(const float* __restrict__ W1,
                                             const float* __restrict__ b1,
                                             const float* __restrict__ W2,
                                             const float* __restrict__ b2,
                                             float* __restrict__ out) {
    extern __shared__ float sm[];
    float* Ws = sm;                      // 256*128
    float* Xs = sm + 2 * HH * HH;        // 8 warps * 4 nodes * 512 (dup of 256)
    for (int i = threadIdx.x; i < 2 * HH * HH / 4; i += 256)
        ((float4*)Ws)[i] = ((const float4*)W1)[i];
    int lane = threadIdx.x & 31, w = threadIdx.x >> 5;
    float4 bb = *(const float4*)&b1[4 * lane];
    float4 w2v = *(const float4*)&W2[4 * lane];
    float b2v = b2[0];
    __syncthreads();
    float* X = Xs + w * (ONT * 2 * 2 * HH);
    int gw = blockIdx.x * ONW + w;
    for (int n0 = gw * ONT; n0 < NN; n0 += 148 * ONW * ONT) {
        #pragma unroll
        for (int i = 0; i < ONT; i++) {
            float4 a = *(const float4*)&d_hA[(n0 + i) * HH + 4 * lane];
            float4 c = *(const float4*)&d_h0[(n0 + i) * HH + 4 * lane];
            float* xr = X + i * 512;
            *(float4*)(xr + 8 * lane)           = make_float4(a.x, a.x, a.y, a.y);
            *(float4*)(xr + 8 * lane + 4)       = make_float4(a.z, a.z, a.w, a.w);
            *(float4*)(xr + 256 + 8 * lane)     = make_float4(c.x, c.x, c.y, c.y);
            *(float4*)(xr + 256 + 8 * lane + 4) = make_float4(c.z, c.z, c.w, c.w);
        }
        __syncwarp();
        unsigned long long acc[ONT][2];
        #pragma unroll
        for (int i = 0; i < ONT; i++) { acc[i][0] = 0ull; acc[i][1] = 0ull; }
        #pragma unroll 4
        for (int k = 0; k < 2 * HH; k++) {
            ulonglong2 wv = *(const ulonglong2*)&Ws[k * HH + 4 * lane];
            #pragma unroll
            for (int i = 0; i < ONT; i++) {
                unsigned long long xk = *(const unsigned long long*)&X[i * 512 + 2 * k];
                fma2(acc[i][0], xk, wv.x);
                fma2(acc[i][1], xk, wv.y);
            }
        }
        #pragma unroll
        for (int i = 0; i < ONT; i++) {
            float2 p0 = up2(acc[i][0]), p1 = up2(acc[i][1]);
            float r0 = fmaxf(p0.x + bb.x, 0.f), r1 = fmaxf(p0.y + bb.y, 0.f);
            float r2 = fmaxf(p1.x + bb.z, 0.f), r3 = fmaxf(p1.y + bb.w, 0.f);
            float p = r0 * w2v.x + r1 * w2v.y + r2 * w2v.z + r3 * w2v.w;
            #pragma unroll
            for (int o = 16; o > 0; o >>= 1) p += __shfl_xor_sync(0xFFFFFFFFu, p, o);
            if (lane == 0) out[n0 + i] = p + b2v;
        }
        __syncwarp();
    }
}

// ---------------- launch ----------------
extern "C" void kernel_launch(void* const* d_in, const int* in_sizes, int n_in,
                              void* d_out, int out_size) {
    (void)in_sizes; (void)n_in; (void)out_size;
    const int*   xidx = (const int*)  d_in[0];
    const float* sel  = (const float*)d_in[1];
    const int*   eidx = (const int*)  d_in[2];
    const int*   et   = (const int*)  d_in[3];
    const int*   epos = (const int*)  d_in[4];
    const float* emb  = (const float*)d_in[5];
    const float* pe   = (const float*)d_in[6];
    const float* Wg   = (const float*)d_in[7];
    const float* bg   = (const float*)d_in[8];
    const float* Wt   = (const float*)d_in[9];
    const float* bt   = (const float*)d_in[10];
    const float* Wih  = (const float*)d_in[11];
    const float* Whh  = (const float*)d_in[12];
    const float* bih  = (const float*)d_in[13];
    const float* bhh  = (const float*)d_in[14];
    const float* W1   = (const float*)d_in[15];
    const float* b1   = (const float*)d_in[16];
    const float* W2   = (const float*)d_in[17];
    const float* b2   = (const float*)d_in[18];
    float* out = (float*)d_out;
    const int* src = eidx;
    const int* dst = eidx + EE;

    const int SM_EDGE = (HH * HH + EWPB * EPW * 2 * HH) * 4;        // 196,608
    const int SM_GRU  = (HH * WTS + GNW * GNT * HH) * 4;            // 215,040
    const int SM_OUT  = (2 * HH * HH + ONW * ONT * 2 * 2 * HH) * 4; // 196,608

    cudaFuncSetAttribute(k_edge, cudaFuncAttributeMaxDynamicSharedMemorySize, SM_EDGE);
    cudaFuncSetAttribute(k_gi,   cudaFuncAttributeMaxDynamicSharedMemorySize, SM_GRU);
    cudaFuncSetAttribute(k_gh,   cudaFuncAttributeMaxDynamicSharedMemorySize, SM_GRU);
    cudaFuncSetAttribute(k_out,  cudaFuncAttributeMaxDynamicSharedMemorySize, SM_OUT);

    // setup: type sort + degrees + h0 + gate table (all once per replay)
    k_init_pad<<<(PADE + 255) / 256, 256>>>();
    k_hist<<<(EE + 255) / 256, 256>>>(et);
    k_off<<<1, 1>>>();
    k_perm<<<(EE + 255) / 256, 256>>>(src, dst, et, epos);
    k_zero_cnt<<<(NN + 255) / 256, 256>>>();
    k_h0<<<(NN * 32 + 255) / 256, 256>>>(xidx, sel, emb);
    k_deg<<<(EE + 255) / 256, 256>>>(dst);
    k_inv<<<(NN + 255) / 256, 256>>>();
    k_gtab<<<NPOS, 128>>>(pe, Wg, bg);

    for (int it = 0; it < GITERS; it++) {
        int flip = it & 1;
        k_zero_agg<<<(NN * HH / 4 + 255) / 256, 256>>>();
        k_edge<<<PADE / EPB, 256, SM_EDGE>>>(Wt, bt, flip);
        k_gi<<<148, 128, SM_GRU>>>(Wih, bih);
        k_gh<<<148, 128, SM_GRU>>>(Whh, bhh, flip);
    }
    k_out<<<148, 256, SM_OUT>>>(W1, b1, W2, b2, out);
}